// round 1
// baseline (speedup 1.0000x reference)
#include <cuda_runtime.h>
#include <cuda_bf16.h>

#define BATCH 16384
#define NEGK  20
#define DIM   128

__global__ void zero_out_kernel(float* out) {
    out[0] = 0.0f;
}

__global__ __launch_bounds__(128, 16)
void i2v_loss_kernel(const int* __restrict__ center,
                     const int* __restrict__ pos,
                     const int* __restrict__ neg,
                     const float* __restrict__ W_in,
                     const float* __restrict__ W_out,
                     float* __restrict__ out)
{
    const int b    = blockIdx.x;
    const int lane = threadIdx.x & 31;
    const int wid  = threadIdx.x >> 5;

    // Load this block's center embedding row: 32 lanes x float4 = 128 floats.
    // All 4 warps load the same row; warps 1-3 hit L1.
    const size_t crow = (size_t)center[b] * DIM;
    const float4 c = *reinterpret_cast<const float4*>(W_in + crow + 4 * lane);

    float loss = 0.0f;

    // 21 targets: t=0 is the positive sample, t=1..20 are negatives.
    // Warp w handles t in {w, w+4, w+8, ...}.
    #pragma unroll
    for (int t = wid; t < 1 + NEGK; t += 4) {
        const int row_idx = (t == 0) ? pos[b] : neg[b * NEGK + (t - 1)];
        const size_t row = (size_t)row_idx * DIM;
        const float4 v = *reinterpret_cast<const float4*>(W_out + row + 4 * lane);

        float p = c.x * v.x + c.y * v.y + c.z * v.z + c.w * v.w;
        // full warp butterfly reduce: every lane ends with the dot product
        #pragma unroll
        for (int off = 16; off > 0; off >>= 1)
            p += __shfl_xor_sync(0xffffffffu, p, off);

        if (lane == 0) {
            // pos: -log(sigmoid(p)+eps); neg: -log(sigmoid(-p)+eps)
            const float s   = (t == 0) ? p : -p;
            const float sig = 1.0f / (1.0f + __expf(-s));
            loss += -logf(sig + 1e-10f);
        }
    }

    __shared__ float wsum[4];
    if (lane == 0) wsum[wid] = loss;
    __syncthreads();

    if (threadIdx.x == 0) {
        const float blk = wsum[0] + wsum[1] + wsum[2] + wsum[3];
        atomicAdd(out, blk * (1.0f / (float)BATCH));
    }
}

extern "C" void kernel_launch(void* const* d_in, const int* in_sizes, int n_in,
                              void* d_out, int out_size)
{
    const int*   center = (const int*)  d_in[0];
    const int*   pos    = (const int*)  d_in[1];
    const int*   neg    = (const int*)  d_in[2];
    const float* W_in   = (const float*)d_in[3];
    const float* W_out  = (const float*)d_in[4];
    float* out = (float*)d_out;

    zero_out_kernel<<<1, 1>>>(out);
    i2v_loss_kernel<<<BATCH, 128>>>(center, pos, neg, W_in, W_out, out);
}

// round 2
// speedup vs baseline: 1.1585x; 1.1585x over previous
#include <cuda_runtime.h>
#include <cuda_bf16.h>

#define BATCH 16384
#define NEGK  20
#define DIM   128

__global__ void zero_out_kernel(float* out) {
    out[0] = 0.0f;
}

__global__ __launch_bounds__(128, 8)
void i2v_loss_kernel(const int* __restrict__ center,
                     const int* __restrict__ pos,
                     const int* __restrict__ neg,
                     const float* __restrict__ W_in,
                     const float* __restrict__ W_out,
                     float* __restrict__ out)
{
    const int b    = blockIdx.x;
    const int lane = threadIdx.x & 31;
    const int wid  = threadIdx.x >> 5;

    // ---- phase 0: gather the target indices for this warp ----------------
    // Warp w owns targets t = w, w+4, w+8, ... (< 21). That's 6 targets for
    // warp 0 (t=0 is the positive sample), 5 for warps 1-3.
    // Lane k holds the index for this warp's k-th target.
    const int t_lane = wid + 4 * lane;
    int myidx = 0;
    if (lane < 6 && t_lane < 1 + NEGK)
        myidx = (t_lane == 0) ? pos[b] : neg[b * NEGK + t_lane - 1];

    const int nt = (wid == 0) ? 6 : 5;

    // ---- phase 1: issue ALL row loads back-to-back (MLP ~ 7/warp) --------
    const size_t crow = (size_t)center[b] * DIM;
    const float4 c = *reinterpret_cast<const float4*>(W_in + crow + 4 * lane);

    float4 v[6];
    #pragma unroll
    for (int k = 0; k < 6; ++k) {
        const int idx = __shfl_sync(0xffffffffu, myidx, k);
        if (k < nt)
            v[k] = *reinterpret_cast<const float4*>(
                       W_out + (size_t)idx * DIM + 4 * lane);
    }

    // ---- phase 2: per-lane partial dots -----------------------------------
    float p[6];
    #pragma unroll
    for (int k = 0; k < 6; ++k)
        p[k] = (k < nt)
             ? (c.x * v[k].x + c.y * v[k].y + c.z * v[k].z + c.w * v[k].w)
             : 0.0f;

    // ---- phase 3: 6 interleaved butterfly reductions (chains pipeline) ----
    #pragma unroll
    for (int off = 16; off > 0; off >>= 1) {
        #pragma unroll
        for (int k = 0; k < 6; ++k)
            p[k] += __shfl_xor_sync(0xffffffffu, p[k], off);
    }

    // ---- phase 4: log-sigmoid losses (lane 0, independent MUFU chains) ----
    float loss = 0.0f;
    if (lane == 0) {
        #pragma unroll
        for (int k = 0; k < 6; ++k) {
            if (k < nt) {
                const int   t   = wid + 4 * k;
                const float s   = (t == 0) ? p[k] : -p[k];
                const float sig = 1.0f / (1.0f + __expf(-s));
                loss += -logf(sig + 1e-10f);
            }
        }
    }

    __shared__ float wsum[4];
    if (lane == 0) wsum[wid] = loss;
    __syncthreads();

    if (threadIdx.x == 0) {
        const float blk = wsum[0] + wsum[1] + wsum[2] + wsum[3];
        atomicAdd(out, blk * (1.0f / (float)BATCH));
    }
}

extern "C" void kernel_launch(void* const* d_in, const int* in_sizes, int n_in,
                              void* d_out, int out_size)
{
    const int*   center = (const int*)  d_in[0];
    const int*   pos    = (const int*)  d_in[1];
    const int*   neg    = (const int*)  d_in[2];
    const float* W_in   = (const float*)d_in[3];
    const float* W_out  = (const float*)d_in[4];
    float* out = (float*)d_out;

    zero_out_kernel<<<1, 1>>>(out);
    i2v_loss_kernel<<<BATCH, 128>>>(center, pos, neg, W_in, W_out, out);
}

// round 3
// speedup vs baseline: 1.3464x; 1.1622x over previous
#include <cuda_runtime.h>
#include <cuda_bf16.h>

#define BATCH 16384
#define NEGK  20
#define NT    (NEGK + 1)      // 21 targets per batch element
#define DIM   128
#define WPB   8               // warps (batch elements) per block

__global__ void zero_out_kernel(float* out) {
    out[0] = 0.0f;
}

__device__ __forceinline__ float dot4(const float4 a, const float4 b) {
    return a.x * b.x + a.y * b.y + a.z * b.z + a.w * b.w;
}

__global__ __launch_bounds__(WPB * 32)
void i2v_loss_kernel(const int* __restrict__ center,
                     const int* __restrict__ pos,
                     const int* __restrict__ neg,
                     const float* __restrict__ W_in,
                     const float* __restrict__ W_out,
                     float* __restrict__ out)
{
    const unsigned FULL = 0xffffffffu;
    const int lane = threadIdx.x & 31;
    const int wid  = threadIdx.x >> 5;
    const int b    = blockIdx.x * WPB + wid;   // one warp == one batch element

    // ---- gather the 21 target indices: lane l holds index for target l ----
    int myidx = 0;
    if (lane == 0)       myidx = pos[b];
    else if (lane < NT)  myidx = neg[b * NEGK + lane - 1];

    // ---- center row (loaded exactly once per batch element) ---------------
    const size_t crow = (size_t)center[b] * DIM;
    const float4 c = *reinterpret_cast<const float4*>(W_in + crow + 4 * lane);

    float p[NT];

    // ---- wave A: 11 row loads back-to-back, then partial dots -------------
    {
        float4 v[11];
        #pragma unroll
        for (int k = 0; k < 11; ++k) {
            const int idx = __shfl_sync(FULL, myidx, k);
            v[k] = *reinterpret_cast<const float4*>(
                       W_out + (size_t)idx * DIM + 4 * lane);
        }
        #pragma unroll
        for (int k = 0; k < 11; ++k)
            p[k] = dot4(c, v[k]);
    }

    // ---- wave B: remaining 10 rows ----------------------------------------
    {
        float4 v[10];
        #pragma unroll
        for (int k = 0; k < 10; ++k) {
            const int idx = __shfl_sync(FULL, myidx, 11 + k);
            v[k] = *reinterpret_cast<const float4*>(
                       W_out + (size_t)idx * DIM + 4 * lane);
        }
        #pragma unroll
        for (int k = 0; k < 10; ++k)
            p[11 + k] = dot4(c, v[k]);
    }

    // ---- 21 interleaved butterfly reductions (chains pipeline) ------------
    #pragma unroll
    for (int off = 16; off > 0; off >>= 1) {
        #pragma unroll
        for (int k = 0; k < NT; ++k)
            p[k] += __shfl_xor_sync(FULL, p[k], off);
    }

    // ---- per-lane loss: lane l handles target l (parallel MUFU) -----------
    float mine = 0.0f;
    #pragma unroll
    for (int k = 0; k < NT; ++k)
        if (lane == k) mine = p[k];

    float loss = 0.0f;
    if (lane < NT) {
        const float s   = (lane == 0) ? mine : -mine;   // pos vs neg sign
        const float sig = 1.0f / (1.0f + __expf(-s));
        loss = -logf(sig + 1e-10f);
    }

    // ---- reduce loss across the warp ---------------------------------------
    #pragma unroll
    for (int off = 16; off > 0; off >>= 1)
        loss += __shfl_xor_sync(FULL, loss, off);

    // ---- block accumulate, one atomic per block ----------------------------
    __shared__ float wsum[WPB];
    if (lane == 0) wsum[wid] = loss;
    __syncthreads();

    if (threadIdx.x == 0) {
        float blk = 0.0f;
        #pragma unroll
        for (int w = 0; w < WPB; ++w) blk += wsum[w];
        atomicAdd(out, blk * (1.0f / (float)BATCH));
    }
}

extern "C" void kernel_launch(void* const* d_in, const int* in_sizes, int n_in,
                              void* d_out, int out_size)
{
    const int*   center = (const int*)  d_in[0];
    const int*   pos    = (const int*)  d_in[1];
    const int*   neg    = (const int*)  d_in[2];
    const float* W_in   = (const float*)d_in[3];
    const float* W_out  = (const float*)d_in[4];
    float* out = (float*)d_out;

    zero_out_kernel<<<1, 1>>>(out);
    i2v_loss_kernel<<<BATCH / WPB, WPB * 32>>>(center, pos, neg, W_in, W_out, out);
}